// round 14
// baseline (speedup 1.0000x reference)
#include <cuda_runtime.h>
#include <cuda_fp16.h>
#include <math.h>
#include <stdint.h>

#define BATCH 32768
#define FEAT  784
#define FV    196
#define NITER 8
#define BROWS (BATCH * 4)        // 131072 capsule rows

#define KPAD_CAP 208             // capsule K padded (3*64 + 16)
#define NPAD_CAP 224             // capsule weight buffer rows (pads zero)

// ----------------------------- scratch ------------------------------------
__device__ __align__(256) __half g_hhi [(size_t)BROWS * KPAD_CAP];
__device__ __align__(256) __half g_gthi[NPAD_CAP * KPAD_CAP];
__device__ __align__(256) float  g_g2[KPAD_CAP];                  // pads stay 0
__device__ __align__(256) __half g_w3hi[NPAD_CAP * KPAD_CAP];
__device__ __align__(256) __half g_wd1hi[FEAT * FEAT];
__device__ __align__(256) float  g_wop[10 * FEAT];
__device__ __align__(256) float  g_bop[16];
__device__ __align__(256) __half g_dhi[(size_t)BATCH * FEAT];
__device__ __align__(256) __half g_thi[(size_t)BATCH * FEAT];

// ----------------------------- PTX helpers --------------------------------
__device__ __forceinline__ uint32_t smem_u32(const void* p) {
    uint32_t a;
    asm("{ .reg .u64 t; cvta.to.shared.u64 t, %1; cvt.u32.u64 %0, t; }" : "=r"(a) : "l"(p));
    return a;
}
__device__ __forceinline__ void cp_async16(uint32_t dst, const void* src) {
    asm volatile("cp.async.cg.shared.global [%0], [%1], 16;" :: "r"(dst), "l"(src));
}
__device__ __forceinline__ void ldsm_x4(uint32_t* r, uint32_t addr) {
    asm volatile("ldmatrix.sync.aligned.m8n8.x4.shared.b16 {%0,%1,%2,%3}, [%4];"
                 : "=r"(r[0]), "=r"(r[1]), "=r"(r[2]), "=r"(r[3]) : "r"(addr));
}
__device__ __forceinline__ void ldsm_x2(uint32_t* r, uint32_t addr) {
    asm volatile("ldmatrix.sync.aligned.m8n8.x2.shared.b16 {%0,%1}, [%2];"
                 : "=r"(r[0]), "=r"(r[1]) : "r"(addr));
}
__device__ __forceinline__ void mma16816(float* c, const uint32_t* a, const uint32_t* b) {
    asm volatile("mma.sync.aligned.m16n8k16.row.col.f32.f16.f16.f32 "
                 "{%0,%1,%2,%3}, {%4,%5,%6,%7}, {%8,%9}, {%0,%1,%2,%3};"
                 : "+f"(c[0]), "+f"(c[1]), "+f"(c[2]), "+f"(c[3])
                 : "r"(a[0]), "r"(a[1]), "r"(a[2]), "r"(a[3]), "r"(b[0]), "r"(b[1]));
}
// swizzle for 128B rows, 16B granules
__device__ __forceinline__ uint32_t swz(int r, int g) {
    return (uint32_t)r * 128u + ((uint32_t)(g ^ (r & 7)) << 4);
}
// load 8 halves -> 8 floats (generic pointer)
__device__ __forceinline__ void ld8h(float* f, const __half* p) {
    uint4 q = *(const uint4*)p;
    const __half2* h = reinterpret_cast<const __half2*>(&q);
#pragma unroll
    for (int i = 0; i < 4; i++) {
        float2 a = __half22float2(h[i]);
        f[2*i] = a.x; f[2*i+1] = a.y;
    }
}

// ================== persistent fused capsule (all 8 iterations) ============
// One 512-thread block owns 128 rows (32 batches).
// Resident in smem: A (h state, updated in place), full Gt.
// N computed = 200 (cols 200-223 of the padded weights are exact zeros and
// are skipped): wn=0..2 warps do 7 n8-frags (56 cols), wn=3 does 4 (32 cols).
#define SMEM_A_OFF 0u
#define A_CHUNK    16384u               // one 64-col chunk of A (swz layout)
#define GT_OFF     65536u
#define W_CHUNK    28672u               // 224 rows x 128B
#define GT_TAIL    (GT_OFF + 3u * W_CHUNK)          // 151552, 224 x 32B
#define SMEM_Z_OFF 158720u              // 128 x 224 fp16, row stride 448B
#define W_STAGE    28672u               // W3 stages alias the z region
#define SMEM_P_OFF 216064u              // 32 batches x 16 floats
#define CAP_SMEM   218112

__global__ __launch_bounds__(512, 1)
void capsule_persist(const __half* __restrict__ A,
                     const __half* __restrict__ Gt,
                     const __half* __restrict__ W3,
                     const float* __restrict__ g2,
                     const float* __restrict__ b3,
                     __half* __restrict__ D)
{
    extern __shared__ char smem[];
    const uint32_t sb = smem_u32(smem);
    const int tid = threadIdx.x;
    const int lane = tid & 31;
    const int wid = tid >> 5;        // 0..15
    const int wm = wid & 3;          // rows wm*32
    const int wn = wid >> 2;         // cols wn*56 (0..3)
    const int m0 = blockIdx.x * 128;
    const int nfc = (wn == 3) ? 4 : 7;       // fragments this warp computes
    const int npair = nfc >> 1;              // x4 pair loads (3 or 2)
    const int nodd = nfc & 1;                // trailing x2 load (1 or 0)

    float acc[2][7][4];

    // stream W3 chunk ch into z-region stage (ch&1)
    auto load_w3 = [&](int ch) {
        const uint32_t s = sb + SMEM_Z_OFF + (uint32_t)(ch & 1) * W_STAGE;
        if (ch < 3) {
#pragma unroll
            for (int i = 0; i < 4; i++) {          // 224 rows x 8 granules = 1792
                int idx = tid + i * 512;
                if (idx < 1792) {
                    int r = idx >> 3, g = idx & 7;
                    cp_async16(s + swz(r, g), W3 + (size_t)r * KPAD_CAP + (ch << 6) + g * 8);
                }
            }
        } else {
            if (tid < 448) {                       // tail: 224 x 2 granules
                int r = tid >> 1, g = tid & 1;
                cp_async16(s + swz(r, g), W3 + (size_t)r * KPAD_CAP + 192 + g * 8);
            }
        }
        asm volatile("cp.async.commit_group;");
    };

    // one 16-col k-step; both operands in swizzled layouts; nfc-trimmed B
    auto compute_ks = [&](uint32_t sA, uint32_t sW, int ks) {
        uint32_t ah[2][4], bh[7][2];
#pragma unroll
        for (int mf = 0; mf < 2; mf++) {
            int r = wm * 32 + mf * 16 + (lane & 15);
            int g = ks * 2 + (lane >> 4);
            ldsm_x4(ah[mf], sA + swz(r, g));
        }
#pragma unroll
        for (int p = 0; p < 3; p++) {
            if (p < npair) {
                int r = wn * 56 + p * 16 + (lane & 7) + ((lane >> 4) & 1) * 8;
                int g = ks * 2 + ((lane >> 3) & 1);
                uint32_t t4[4];
                ldsm_x4(t4, sW + swz(r, g));
                bh[2*p][0] = t4[0]; bh[2*p][1] = t4[1];
                bh[2*p+1][0] = t4[2]; bh[2*p+1][1] = t4[3];
            }
        }
        if (nodd) {
            int l15 = lane & 15;
            int r = wn * 56 + 48 + (l15 & 7);
            int g = ks * 2 + ((l15 >> 3) & 1);
            ldsm_x2(bh[6], sW + swz(r, g));
        }
#pragma unroll
        for (int mf = 0; mf < 2; mf++)
#pragma unroll
            for (int nf = 0; nf < 7; nf++)
                if (nf < nfc)
                    mma16816(acc[mf][nf], ah[mf], bh[nf]);
    };

    // tail k-step against the compact Gt tail (32B row stride)
    auto compute_tail_gt = [&]() {
        uint32_t ah[2][4], bh[7][2];
        const uint32_t sA = sb + SMEM_A_OFF + 3u * A_CHUNK;
        const uint32_t sT = sb + GT_TAIL;
#pragma unroll
        for (int mf = 0; mf < 2; mf++) {
            int r = wm * 32 + mf * 16 + (lane & 15);
            int g = (lane >> 4);
            ldsm_x4(ah[mf], sA + swz(r, g));
        }
#pragma unroll
        for (int p = 0; p < 3; p++) {
            if (p < npair) {
                int r = wn * 56 + p * 16 + (lane & 7) + ((lane >> 4) & 1) * 8;
                int g = ((lane >> 3) & 1);
                uint32_t t4[4];
                ldsm_x4(t4, sT + (uint32_t)r * 32u + (uint32_t)g * 16u);
                bh[2*p][0] = t4[0]; bh[2*p][1] = t4[1];
                bh[2*p+1][0] = t4[2]; bh[2*p+1][1] = t4[3];
            }
        }
        if (nodd) {
            int l15 = lane & 15;
            int r = wn * 56 + 48 + (l15 & 7);
            int g = ((l15 >> 3) & 1);
            ldsm_x2(bh[6], sT + (uint32_t)r * 32u + (uint32_t)g * 16u);
        }
#pragma unroll
        for (int mf = 0; mf < 2; mf++)
#pragma unroll
            for (int nf = 0; nf < 7; nf++)
                if (nf < nfc)
                    mma16816(acc[mf][nf], ah[mf], bh[nf]);
    };

    auto zero_acc = [&]() {
#pragma unroll
        for (int i = 0; i < 2; i++)
#pragma unroll
            for (int j = 0; j < 7; j++)
#pragma unroll
                for (int v = 0; v < 4; v++) acc[i][j][v] = 0.f;
    };

    // ---- one-time loads: A (128 x 26 granules) + Gt resident (224 x 26) ----
    for (int i = 0; i < 7; i++) {
        int idx = tid + i * 512;
        if (idx < 128 * 26) {
            int r = idx / 26, gg = idx - r * 26;
            int c = gg >> 3, g = gg & 7;
            cp_async16(sb + SMEM_A_OFF + (uint32_t)c * A_CHUNK + swz(r, g),
                       A + (size_t)(m0 + r) * KPAD_CAP + gg * 8);
        }
    }
    for (int i = 0; i < 12; i++) {
        int idx = tid + i * 512;
        if (idx < 224 * 26) {
            int r = idx / 26, gg = idx - r * 26;
            uint32_t dst;
            if (gg < 24) dst = sb + GT_OFF + (uint32_t)(gg >> 3) * W_CHUNK + swz(r, gg & 7);
            else         dst = sb + GT_TAIL + (uint32_t)r * 32u + (uint32_t)(gg - 24) * 16u;
            cp_async16(dst, Gt + (size_t)r * KPAD_CAP + gg * 8);
        }
    }
    asm volatile("cp.async.commit_group;");
    asm volatile("cp.async.wait_group 0;");
    __syncthreads();

    for (int it = 0; it < NITER; it++) {
        const int last = (it == NITER - 1);

        // ============ phase 1: z = A @ Gt^T (all resident, NO syncs) ======
        zero_acc();
#pragma unroll
        for (int ch = 0; ch < 3; ch++)
#pragma unroll
            for (int ks = 0; ks < 4; ks++)
                compute_ks(sb + SMEM_A_OFF + (uint32_t)ch * A_CHUNK,
                           sb + GT_OFF + (uint32_t)ch * W_CHUNK, ks);
        compute_tail_gt();

        // z -> smem (fp16), cols 0..199 only.
#pragma unroll
        for (int mf = 0; mf < 2; mf++)
#pragma unroll
        for (int nf = 0; nf < 7; nf++) {
            if (nf >= nfc) continue;
#pragma unroll
            for (int hf = 0; hf < 2; hf++) {
                int row = wm * 32 + mf * 16 + hf * 8 + (lane >> 2);
                int col = wn * 56 + nf * 8 + ((lane & 3) << 1);
                __half2 hv = __floats2half2_rn(acc[mf][nf][hf * 2], acc[mf][nf][hf * 2 + 1]);
                *(__half2*)(smem + SMEM_Z_OFF + (uint32_t)row * 448u + (uint32_t)col * 2u) = hv;
            }
        }
        __syncthreads();

        // ============ phase 2: scores + softmax (cols 0..199) ============
#pragma unroll
        for (int bi = 0; bi < 2; bi++) {
            int bb = wid * 2 + bi;
            float s[4][4], beta[4];
#pragma unroll
            for (int t = 0; t < 4; t++) {
                beta[t] = 0.f;
#pragma unroll
                for (int r = 0; r < 4; r++) s[t][r] = 0.f;
            }
            if (lane < 25) {
                float zf[4][8], vf[4][8], gf[8];
                int c = lane >> 3, g = lane & 7;
#pragma unroll
                for (int t = 0; t < 4; t++) {
                    int row = bb * 4 + t;
                    ld8h(zf[t], (const __half*)(smem + SMEM_Z_OFF + (uint32_t)row * 448u + (uint32_t)lane * 16u));
                    ld8h(vf[t], (const __half*)(smem + SMEM_A_OFF + (uint32_t)c * A_CHUNK + swz(row, g)));
                }
                float4 ga = *(const float4*)(g2 + lane * 8);
                float4 gb = *(const float4*)(g2 + lane * 8 + 4);
                gf[0]=ga.x; gf[1]=ga.y; gf[2]=ga.z; gf[3]=ga.w;
                gf[4]=gb.x; gf[5]=gb.y; gf[6]=gb.z; gf[7]=gb.w;
#pragma unroll
                for (int t = 0; t < 4; t++) {
#pragma unroll
                    for (int e = 0; e < 8; e++)
                        beta[t] = fmaf(vf[t][e], gf[e], beta[t]);
#pragma unroll
                    for (int r = 0; r < 4; r++) {
                        float a2 = 0.f;
#pragma unroll
                        for (int e = 0; e < 8; e++)
                            a2 = fmaf(zf[t][e], vf[r][e], a2);
                        s[t][r] = a2;
                    }
                }
            }
#pragma unroll
            for (int t = 0; t < 4; t++) {
#pragma unroll
                for (int off = 16; off > 0; off >>= 1)
                    beta[t] += __shfl_xor_sync(0xffffffffu, beta[t], off);
#pragma unroll
                for (int r = 0; r < 4; r++)
#pragma unroll
                    for (int off = 16; off > 0; off >>= 1)
                        s[t][r] += __shfl_xor_sync(0xffffffffu, s[t][r], off);
            }
            if (lane < 16) {
                int t = lane >> 2;
                float sc[4];
#pragma unroll
                for (int r = 0; r < 4; r++) sc[r] = s[t][r] + beta[r];
                float m = fmaxf(fmaxf(sc[0], sc[1]), fmaxf(sc[2], sc[3]));
                float e0 = expf(sc[0] - m), e1 = expf(sc[1] - m);
                float e2 = expf(sc[2] - m), e3 = expf(sc[3] - m);
                float inv = 1.f / (e0 + e1 + e2 + e3);
                float pe = (lane & 3) == 0 ? e0 : (lane & 3) == 1 ? e1 : (lane & 3) == 2 ? e2 : e3;
                *(float*)(smem + SMEM_P_OFF + (uint32_t)bb * 64u + (uint32_t)lane * 4u) = pe * inv;
            }
        }
        __syncthreads();   // all warps done with z (and probs visible)

        // ============ phase 3: u = A @ W3^T (W3 streamed via z region) ====
        zero_acc();
        load_w3(0);
        for (int ch = 0; ch < 4; ch++) {
            if (ch < 3) { load_w3(ch + 1); asm volatile("cp.async.wait_group 1;"); }
            else        { asm volatile("cp.async.wait_group 0;"); }
            __syncthreads();
            const uint32_t sA = sb + SMEM_A_OFF + (uint32_t)ch * A_CHUNK;
            const uint32_t sW = sb + SMEM_Z_OFF + (uint32_t)(ch & 1) * W_STAGE;
            if (ch < 3) {
#pragma unroll
                for (int ks = 0; ks < 4; ks++) compute_ks(sA, sW, ks);
            } else compute_ks(sA, sW, 0);
            __syncthreads();   // stage reuse + A-read completion before h write
        }

        // epilogue: h[t] = sum_s p[t][s] * (u[s] + b3) -> A smem (or D last)
#pragma unroll
        for (int mf = 0; mf < 2; mf++)
#pragma unroll
        for (int hf = 0; hf < 2; hf++) {
            int br = wm * 32 + mf * 16 + hf * 8 + (lane >> 2);
            int bb = br >> 2, t = br & 3;
            float4 pv = *(const float4*)(smem + SMEM_P_OFF + (uint32_t)bb * 64u + (uint32_t)t * 16u);
            int base = (lane >> 2) & 4;
#pragma unroll
            for (int nf = 0; nf < 7; nf++) {
                if (nf >= nfc) continue;
                int c0 = wn * 56 + nf * 8 + ((lane & 3) << 1);
                float hpair[2];
#pragma unroll
                for (int e = 0; e < 2; e++) {
                    float uv = acc[mf][nf][hf * 2 + e] + ((c0 + e < FV) ? b3[c0 + e] : 0.f);
                    float h = 0.f;
#pragma unroll
                    for (int s2 = 0; s2 < 4; s2++) {
                        float us = __shfl_sync(0xffffffffu, uv, ((base + s2) << 2) | (lane & 3));
                        float ps = (s2 == 0) ? pv.x : (s2 == 1) ? pv.y : (s2 == 2) ? pv.z : pv.w;
                        h = fmaf(ps, us, h);
                    }
                    hpair[e] = h;
                }
                if (c0 < FV) {
                    __half2 hv = __floats2half2_rn(hpair[0], hpair[1]);
                    if (last) {
                        *(__half2*)(D + (size_t)((m0 + br) >> 2) * FEAT + t * FV + c0) = hv;
                    } else {
                        int chk = c0 >> 6, cc = c0 & 63;
                        *(__half2*)(smem + SMEM_A_OFF + (uint32_t)chk * A_CHUNK
                                    + swz(br, cc >> 3) + (uint32_t)(cc & 7) * 2u) = hv;
                    }
                }
            }
        }
        if (!last) __syncthreads();
    }
}

// ----------------------- decoder GEMM (fp16 mma.sync, 2-stage) -------------
#define OFF_W 16384u
#define STAGE_BYTES 30720u
#define SMEM_BYTES 61440

__global__ __launch_bounds__(256, 2)
void gemm_mma(const __half* __restrict__ A, int lda,
              const __half* __restrict__ W, int ldw,
              const float* __restrict__ bias,
              __half* __restrict__ Ch, int ldc, int K, int n_real, int relu)
{
    extern __shared__ char smem[];
    const uint32_t sb = smem_u32(smem);
    const int tid = threadIdx.x;
    const int lane = tid & 31;
    const int wid = tid >> 5;
    const int wm = wid & 3;
    const int wn = wid >> 2;
    const int m0 = blockIdx.y * 128;
    const int n0 = blockIdx.x * 112;
    const int nfull = K >> 6;
    const int nch = nfull + 1;

    float acc[2][7][4];
#pragma unroll
    for (int i = 0; i < 2; i++)
#pragma unroll
        for (int j = 0; j < 7; j++)
#pragma unroll
            for (int v = 0; v < 4; v++) acc[i][j][v] = 0.f;

    auto load_full = [&](int ch) {
        const uint32_t s = sb + (uint32_t)(ch & 1) * STAGE_BYTES;
        const int kc = ch << 6;
#pragma unroll
        for (int i = 0; i < 4; i++) {
            int idx = tid + i * 256;
            int r = idx >> 3, g = idx & 7;
            cp_async16(s + swz(r, g), A + (size_t)(m0 + r) * lda + kc + g * 8);
        }
#pragma unroll
        for (int i = 0; i < 3; i++) {
            int idx = tid + i * 256;
            int r = idx >> 3, g = idx & 7;
            cp_async16(s + OFF_W + swz(r, g), W + (size_t)(n0 + r) * ldw + kc + g * 8);
        }
        {
            int idx = tid + 768;
            if (idx < 896) {
                int r = idx >> 3, g = idx & 7;
                cp_async16(s + OFF_W + swz(r, g), W + (size_t)(n0 + r) * ldw + kc + g * 8);
            }
        }
        asm volatile("cp.async.commit_group;");
    };
    auto load_tail = [&](int ch) {
        const uint32_t s = sb + (uint32_t)(ch & 1) * STAGE_BYTES;
        const int kc = ch << 6;
        {
            int r = tid >> 1, g = tid & 1;
            cp_async16(s + swz(r, g), A + (size_t)(m0 + r) * lda + kc + g * 8);
        }
        if (tid < 224) {
            int r = tid >> 1, g = tid & 1;
            cp_async16(s + OFF_W + swz(r, g), W + (size_t)(n0 + r) * ldw + kc + g * 8);
        }
        asm volatile("cp.async.commit_group;");
    };
    auto compute_ks = [&](uint32_t s, int ks) {
        uint32_t ah[2][4], bh[7][2];
        const uint32_t sw = s + OFF_W;
#pragma unroll
        for (int mf = 0; mf < 2; mf++) {
            int r = wm * 32 + mf * 16 + (lane & 15);
            int g = ks * 2 + (lane >> 4);
            ldsm_x4(ah[mf], s + swz(r, g));
        }
#pragma unroll
        for (int p = 0; p < 3; p++) {
            int r = wn * 56 + p * 16 + (lane & 7) + ((lane >> 4) & 1) * 8;
            int g = ks * 2 + ((lane >> 3) & 1);
            uint32_t t4[4];
            ldsm_x4(t4, sw + swz(r, g));
            bh[2*p][0] = t4[0]; bh[2*p][1] = t4[1];
            bh[2*p+1][0] = t4[2]; bh[2*p+1][1] = t4[3];
        }
        {
            int l15 = lane & 15;
            int r = wn * 56 + 48 + (l15 & 7);
            int g = ks * 2 + ((l15 >> 3) & 1);
            ldsm_x2(bh[6], sw + swz(r, g));
        }
#pragma unroll
        for (int mf = 0; mf < 2; mf++)
#pragma unroll
            for (int nf = 0; nf < 7; nf++)
                mma16816(acc[mf][nf], ah[mf], bh[nf]);
    };

    if (nfull > 0) load_full(0); else load_tail(0);
    for (int ch = 0; ch < nch; ch++) {
        if (ch + 1 < nch) {
            if (ch + 1 < nfull) load_full(ch + 1); else load_tail(ch + 1);
            asm volatile("cp.async.wait_group 1;");
        } else {
            asm volatile("cp.async.wait_group 0;");
        }
        __syncthreads();
        const uint32_t s = sb + (uint32_t)(ch & 1) * STAGE_BYTES;
        if (ch < nfull) {
#pragma unroll
            for (int ks = 0; ks < 4; ks++) compute_ks(s, ks);
        } else {
            compute_ks(s, 0);
        }
        if (ch + 1 < nch) __syncthreads();
    }

#pragma unroll
    for (int mf = 0; mf < 2; mf++)
#pragma unroll
    for (int nf = 0; nf < 7; nf++) {
        int r = m0 + wm * 32 + mf * 16 + (lane >> 2);
        int c = n0 + wn * 56 + nf * 8 + ((lane & 3) << 1);
#pragma unroll
        for (int hf = 0; hf < 2; hf++) {
            int rr = r + hf * 8;
#pragma unroll
            for (int e = 0; e < 2; e++) {
                int cc = c + e;
                if (cc >= n_real) continue;
                float v = acc[mf][nf][hf * 2 + e] + bias[cc];
                if (relu) v = fmaxf(v, 0.f);
                Ch[(size_t)rr * ldc + cc] = __float2half_rn(v);
            }
        }
    }
}

// ----------------------------- precompute ----------------------------------
__global__ void compute_gt(const float* __restrict__ W1, const float* __restrict__ W2,
                           const float* __restrict__ b1,
                           __half* __restrict__ gthi, float* __restrict__ g2)
{
    int idx = blockIdx.x * blockDim.x + threadIdx.x;
    if (idx < KPAD_CAP) {
        float s = 0.f;
        if (idx < FV)
            for (int j = 0; j < FV; j++) s = fmaf(b1[j], W2[(size_t)j * FV + idx], s);
        g2[idx] = s;
    }
    if (idx >= NPAD_CAP * KPAD_CAP) return;
    int n = idx / KPAD_CAP, k = idx % KPAD_CAP;
    float s = 0.f;
    if (n < FV && k < FV) {
        for (int j = 0; j < FV; j++)
            s = fmaf(W1[(size_t)j * FV + k], W2[(size_t)j * FV + n], s);
    }
    gthi[idx] = __float2half_rn(s);
}

__global__ void fold_head(const float* __restrict__ Wo, const float* __restrict__ Wd2,
                          const float* __restrict__ bd2, const float* __restrict__ bo,
                          float* __restrict__ Wop, float* __restrict__ bop)
{
    int idx = blockIdx.x * blockDim.x + threadIdx.x;
    if (idx < 10) {
        float s = bo[idx];
        for (int i = 0; i < FEAT; i++) s = fmaf(Wo[(size_t)idx * FEAT + i], bd2[i], s);
        bop[idx] = s;
    }
    if (idx >= 10 * FEAT) return;
    int j = idx / FEAT, k = idx % FEAT;
    float s = 0.f;
    for (int i = 0; i < FEAT; i++)
        s = fmaf(Wo[(size_t)j * FEAT + i], Wd2[(size_t)i * FEAT + k], s);
    Wop[idx] = s;
}

// ----------------------------- conversions --------------------------------
__global__ void convert_x_kernel(const float* __restrict__ x,
                                 __half* __restrict__ hhi)
{
    size_t idx = (size_t)blockIdx.x * blockDim.x + threadIdx.x;
    if (idx >= (size_t)BROWS * KPAD_CAP) return;
    size_t R = idx / KPAD_CAP;
    int f = (int)(idx % KPAD_CAP);
    hhi[idx] = __float2half_rn((f < FV) ? x[R * FV + f] : 0.f);
}

__global__ void convert_w_kernel(const float* __restrict__ W, int rin, int cin,
                                 __half* __restrict__ hi, int rout, int cout)
{
    int idx = blockIdx.x * blockDim.x + threadIdx.x;
    if (idx >= rout * cout) return;
    int r = idx / cout, c = idx % cout;
    float v = (r < rin && c < cin) ? W[(size_t)r * cin + c] : 0.f;
    hi[idx] = __float2half_rn(v);
}

// ----------------------------- head (fp16 activations, folded Wd2) ---------
__global__ __launch_bounds__(256)
void head_kernel(const __half* __restrict__ T, const float* __restrict__ Wop,
                 const float* __restrict__ bop, float* __restrict__ out)
{
    const int b    = blockIdx.x * 8 + threadIdx.y;
    const int lane = threadIdx.x;
    const __half* a = T + (size_t)b * FEAT;

    float acc[10];
#pragma unroll
    for (int j = 0; j < 10; j++) acc[j] = 0.f;
    for (int kk = lane; kk < FEAT; kk += 32) {
        float av = __half2float(a[kk]);
#pragma unroll
        for (int j = 0; j < 10; j++)
            acc[j] = fmaf(av, Wop[j * FEAT + kk], acc[j]);
    }
#pragma unroll
    for (int j = 0; j < 10; j++)
#pragma unroll
        for (int off = 16; off > 0; off >>= 1)
            acc[j] += __shfl_xor_sync(0xffffffffu, acc[j], off);

    if (lane == 0) {
        float v[10], m = -1e30f;
#pragma unroll
        for (int j = 0; j < 10; j++) { v[j] = acc[j] + bop[j]; m = fmaxf(m, v[j]); }
        float ssum = 0.f;
#pragma unroll
        for (int j = 0; j < 10; j++) { v[j] = expf(v[j] - m); ssum += v[j]; }
        float inv = 1.f / ssum;
#pragma unroll
        for (int j = 0; j < 10; j++) out[(size_t)b * 10 + j] = v[j] * inv;
    }
}

// ---------------------------------------------------------------------------
extern "C" void kernel_launch(void* const* d_in, const int* in_sizes, int n_in,
                              void* d_out, int out_size)
{
    const float* x   = (const float*)d_in[0];
    const float* W1  = (const float*)d_in[1];
    const float* b1  = (const float*)d_in[2];
    const float* W2  = (const float*)d_in[3];
    const float* W3  = (const float*)d_in[5];
    const float* b3  = (const float*)d_in[6];
    const float* Wd1 = (const float*)d_in[7];
    const float* bd1 = (const float*)d_in[8];
    const float* Wd2 = (const float*)d_in[9];
    const float* bd2 = (const float*)d_in[10];
    const float* Wo  = (const float*)d_in[11];
    const float* bo  = (const float*)d_in[12];
    float* out = (float*)d_out;

    cudaFuncSetAttribute(capsule_persist, cudaFuncAttributeMaxDynamicSharedMemorySize, CAP_SMEM);
    cudaFuncSetAttribute(gemm_mma, cudaFuncAttributeMaxDynamicSharedMemorySize, SMEM_BYTES);

    __half *hhi, *gthi, *w3hi, *wd1hi, *dhi, *thi;
    float *g2, *wop, *bop;
    cudaGetSymbolAddress((void**)&hhi, g_hhi);
    cudaGetSymbolAddress((void**)&g2, g_g2);
    cudaGetSymbolAddress((void**)&gthi, g_gthi);
    cudaGetSymbolAddress((void**)&w3hi, g_w3hi);
    cudaGetSymbolAddress((void**)&wd1hi, g_wd1hi);
    cudaGetSymbolAddress((void**)&wop, g_wop);
    cudaGetSymbolAddress((void**)&bop, g_bop);
    cudaGetSymbolAddress((void**)&dhi, g_dhi);
    cudaGetSymbolAddress((void**)&thi, g_thi);

    // precompute + conversions
    convert_x_kernel<<<(int)(((size_t)BROWS * KPAD_CAP + 255) / 256), 256>>>(x, hhi);
    int wcap = NPAD_CAP * KPAD_CAP;
    compute_gt<<<(wcap + 255) / 256, 256>>>(W1, W2, b1, gthi, g2);
    convert_w_kernel<<<(wcap + 255) / 256, 256>>>(W3, FV, FV, w3hi, NPAD_CAP, KPAD_CAP);

    // all 8 capsule iterations in ONE launch; A + Gt resident in smem
    capsule_persist<<<BROWS / 128, 512, CAP_SMEM>>>(hhi, gthi, w3hi, g2, b3, dhi);

    // decoder precompute
    int wdec = FEAT * FEAT;
    convert_w_kernel<<<(wdec + 255) / 256, 256>>>(Wd1, FEAT, FEAT, wd1hi, FEAT, FEAT);
    fold_head<<<(10 * FEAT + 255) / 256, 256>>>(Wo, Wd2, bd2, bo, wop, bop);

    // decoder layer 1 (fp16) + folded head
    const dim3 gdec(7, BATCH / 128);
    gemm_mma<<<gdec, 256, SMEM_BYTES>>>(dhi, FEAT, wd1hi, FEAT, bd1,
                                        thi, FEAT, FEAT, FEAT, 1);
    head_kernel<<<BATCH / 8, dim3(32, 8)>>>(thi, wop, bop, out);
}

// round 15
// speedup vs baseline: 1.0782x; 1.0782x over previous
#include <cuda_runtime.h>
#include <cuda_fp16.h>
#include <math.h>
#include <stdint.h>

#define BATCH 32768
#define FEAT  784
#define FV    196
#define NITER 8
#define BROWS (BATCH * 4)        // 131072 capsule rows

#define KPAD_CAP 208             // capsule K padded (3*64 + 16)
#define NPAD_CAP 224             // capsule weight buffer rows (pads zero)

// ----------------------------- scratch ------------------------------------
__device__ __align__(256) __half g_hhi [(size_t)BROWS * KPAD_CAP];
__device__ __align__(256) __half g_gthi[NPAD_CAP * KPAD_CAP];
__device__ __align__(256) float  g_g2[KPAD_CAP];                  // pads stay 0
__device__ __align__(256) __half g_w3hi[NPAD_CAP * KPAD_CAP];
__device__ __align__(256) __half g_wd1hi[FEAT * FEAT];
__device__ __align__(256) float  g_wop[10 * FEAT];
__device__ __align__(256) float  g_bop[16];
__device__ __align__(256) __half g_dhi[(size_t)BATCH * FEAT];
__device__ __align__(256) __half g_thi[(size_t)BATCH * FEAT];

// ----------------------------- PTX helpers --------------------------------
__device__ __forceinline__ uint32_t smem_u32(const void* p) {
    uint32_t a;
    asm("{ .reg .u64 t; cvta.to.shared.u64 t, %1; cvt.u32.u64 %0, t; }" : "=r"(a) : "l"(p));
    return a;
}
__device__ __forceinline__ void cp_async16(uint32_t dst, const void* src) {
    asm volatile("cp.async.cg.shared.global [%0], [%1], 16;" :: "r"(dst), "l"(src));
}
__device__ __forceinline__ void ldsm_x4(uint32_t* r, uint32_t addr) {
    asm volatile("ldmatrix.sync.aligned.m8n8.x4.shared.b16 {%0,%1,%2,%3}, [%4];"
                 : "=r"(r[0]), "=r"(r[1]), "=r"(r[2]), "=r"(r[3]) : "r"(addr));
}
__device__ __forceinline__ void ldsm_x2(uint32_t* r, uint32_t addr) {
    asm volatile("ldmatrix.sync.aligned.m8n8.x2.shared.b16 {%0,%1}, [%2];"
                 : "=r"(r[0]), "=r"(r[1]) : "r"(addr));
}
__device__ __forceinline__ void mma16816(float* c, const uint32_t* a, const uint32_t* b) {
    asm volatile("mma.sync.aligned.m16n8k16.row.col.f32.f16.f16.f32 "
                 "{%0,%1,%2,%3}, {%4,%5,%6,%7}, {%8,%9}, {%0,%1,%2,%3};"
                 : "+f"(c[0]), "+f"(c[1]), "+f"(c[2]), "+f"(c[3])
                 : "r"(a[0]), "r"(a[1]), "r"(a[2]), "r"(a[3]), "r"(b[0]), "r"(b[1]));
}
// swizzle for 128B rows, 16B granules
__device__ __forceinline__ uint32_t swz(int r, int g) {
    return (uint32_t)r * 128u + ((uint32_t)(g ^ (r & 7)) << 4);
}
// load 8 halves -> 8 floats (generic pointer)
__device__ __forceinline__ void ld8h(float* f, const __half* p) {
    uint4 q = *(const uint4*)p;
    const __half2* h = reinterpret_cast<const __half2*>(&q);
#pragma unroll
    for (int i = 0; i < 4; i++) {
        float2 a = __half22float2(h[i]);
        f[2*i] = a.x; f[2*i+1] = a.y;
    }
}

// ================== persistent fused capsule (all 8 iterations) ============
// One 512-thread block owns 128 rows (32 batches).
// Resident in smem: A (h state, updated in place), full Gt.
// N computed = 200: warps wn=0..2 do 7 n8-frags (static), wn=3 does 4 (static).
#define SMEM_A_OFF 0u
#define A_CHUNK    16384u               // one 64-col chunk of A (swz layout)
#define GT_OFF     65536u
#define W_CHUNK    28672u               // 224 rows x 128B
#define GT_TAIL    (GT_OFF + 3u * W_CHUNK)          // 151552, 224 x 32B
#define SMEM_Z_OFF 158720u              // 128 x 224 fp16, row stride 448B
#define W_STAGE    28672u               // W3 stages alias the z region
#define SMEM_P_OFF 216064u              // 32 batches x 16 floats
#define CAP_SMEM   218112

__global__ __launch_bounds__(512, 1)
void capsule_persist(const __half* __restrict__ A,
                     const __half* __restrict__ Gt,
                     const __half* __restrict__ W3,
                     const float* __restrict__ g2,
                     const float* __restrict__ b3,
                     __half* __restrict__ D)
{
    extern __shared__ char smem[];
    const uint32_t sb = smem_u32(smem);
    const int tid = threadIdx.x;
    const int lane = tid & 31;
    const int wid = tid >> 5;        // 0..15
    const int wm = wid & 3;          // rows wm*32
    const int wn = wid >> 2;         // cols wn*56 (0..3)
    const int m0 = blockIdx.x * 128;
    const bool full_n = (wn < 3);    // warp-uniform
    const int nfc = full_n ? 7 : 4;  // used only in cold epilogue code

    float acc[2][7][4];

    // stream W3 chunk ch into z-region stage (ch&1)
    auto load_w3 = [&](int ch) {
        const uint32_t s = sb + SMEM_Z_OFF + (uint32_t)(ch & 1) * W_STAGE;
        if (ch < 3) {
#pragma unroll
            for (int i = 0; i < 4; i++) {          // 224 rows x 8 granules = 1792
                int idx = tid + i * 512;
                if (idx < 1792) {
                    int r = idx >> 3, g = idx & 7;
                    cp_async16(s + swz(r, g), W3 + (size_t)r * KPAD_CAP + (ch << 6) + g * 8);
                }
            }
        } else {
            if (tid < 448) {                       // tail: 224 x 2 granules
                int r = tid >> 1, g = tid & 1;
                cp_async16(s + swz(r, g), W3 + (size_t)r * KPAD_CAP + 192 + g * 8);
            }
        }
        asm volatile("cp.async.commit_group;");
    };

    // ---- static k-step bodies (7-frag and 4-frag variants) ----
    auto compute_ks7 = [&](uint32_t sA, uint32_t sW, int ks) {
        uint32_t ah[2][4], bh[7][2];
#pragma unroll
        for (int mf = 0; mf < 2; mf++) {
            int r = wm * 32 + mf * 16 + (lane & 15);
            int g = ks * 2 + (lane >> 4);
            ldsm_x4(ah[mf], sA + swz(r, g));
        }
#pragma unroll
        for (int p = 0; p < 3; p++) {
            int r = wn * 56 + p * 16 + (lane & 7) + ((lane >> 4) & 1) * 8;
            int g = ks * 2 + ((lane >> 3) & 1);
            uint32_t t4[4];
            ldsm_x4(t4, sW + swz(r, g));
            bh[2*p][0] = t4[0]; bh[2*p][1] = t4[1];
            bh[2*p+1][0] = t4[2]; bh[2*p+1][1] = t4[3];
        }
        {
            int l15 = lane & 15;
            int r = wn * 56 + 48 + (l15 & 7);
            int g = ks * 2 + ((l15 >> 3) & 1);
            ldsm_x2(bh[6], sW + swz(r, g));
        }
#pragma unroll
        for (int mf = 0; mf < 2; mf++)
#pragma unroll
            for (int nf = 0; nf < 7; nf++)
                mma16816(acc[mf][nf], ah[mf], bh[nf]);
    };
    auto compute_ks4 = [&](uint32_t sA, uint32_t sW, int ks) {
        uint32_t ah[2][4], bh[4][2];
#pragma unroll
        for (int mf = 0; mf < 2; mf++) {
            int r = wm * 32 + mf * 16 + (lane & 15);
            int g = ks * 2 + (lane >> 4);
            ldsm_x4(ah[mf], sA + swz(r, g));
        }
#pragma unroll
        for (int p = 0; p < 2; p++) {
            int r = 168 + p * 16 + (lane & 7) + ((lane >> 4) & 1) * 8;
            int g = ks * 2 + ((lane >> 3) & 1);
            uint32_t t4[4];
            ldsm_x4(t4, sW + swz(r, g));
            bh[2*p][0] = t4[0]; bh[2*p][1] = t4[1];
            bh[2*p+1][0] = t4[2]; bh[2*p+1][1] = t4[3];
        }
#pragma unroll
        for (int mf = 0; mf < 2; mf++)
#pragma unroll
            for (int nf = 0; nf < 4; nf++)
                mma16816(acc[mf][nf], ah[mf], bh[nf]);
    };

    // Gt tail variants (compact 32B row stride)
    auto tail7 = [&]() {
        uint32_t ah[2][4], bh[7][2];
        const uint32_t sA = sb + SMEM_A_OFF + 3u * A_CHUNK;
        const uint32_t sT = sb + GT_TAIL;
#pragma unroll
        for (int mf = 0; mf < 2; mf++) {
            int r = wm * 32 + mf * 16 + (lane & 15);
            ldsm_x4(ah[mf], sA + swz(r, lane >> 4));
        }
#pragma unroll
        for (int p = 0; p < 3; p++) {
            int r = wn * 56 + p * 16 + (lane & 7) + ((lane >> 4) & 1) * 8;
            int g = ((lane >> 3) & 1);
            uint32_t t4[4];
            ldsm_x4(t4, sT + (uint32_t)r * 32u + (uint32_t)g * 16u);
            bh[2*p][0] = t4[0]; bh[2*p][1] = t4[1];
            bh[2*p+1][0] = t4[2]; bh[2*p+1][1] = t4[3];
        }
        {
            int l15 = lane & 15;
            int r = wn * 56 + 48 + (l15 & 7);
            int g = ((l15 >> 3) & 1);
            ldsm_x2(bh[6], sT + (uint32_t)r * 32u + (uint32_t)g * 16u);
        }
#pragma unroll
        for (int mf = 0; mf < 2; mf++)
#pragma unroll
            for (int nf = 0; nf < 7; nf++)
                mma16816(acc[mf][nf], ah[mf], bh[nf]);
    };
    auto tail4 = [&]() {
        uint32_t ah[2][4], bh[4][2];
        const uint32_t sA = sb + SMEM_A_OFF + 3u * A_CHUNK;
        const uint32_t sT = sb + GT_TAIL;
#pragma unroll
        for (int mf = 0; mf < 2; mf++) {
            int r = wm * 32 + mf * 16 + (lane & 15);
            ldsm_x4(ah[mf], sA + swz(r, lane >> 4));
        }
#pragma unroll
        for (int p = 0; p < 2; p++) {
            int r = 168 + p * 16 + (lane & 7) + ((lane >> 4) & 1) * 8;
            int g = ((lane >> 3) & 1);
            uint32_t t4[4];
            ldsm_x4(t4, sT + (uint32_t)r * 32u + (uint32_t)g * 16u);
            bh[2*p][0] = t4[0]; bh[2*p][1] = t4[1];
            bh[2*p+1][0] = t4[2]; bh[2*p+1][1] = t4[3];
        }
#pragma unroll
        for (int mf = 0; mf < 2; mf++)
#pragma unroll
            for (int nf = 0; nf < 4; nf++)
                mma16816(acc[mf][nf], ah[mf], bh[nf]);
    };

    auto zero_acc = [&]() {
#pragma unroll
        for (int i = 0; i < 2; i++)
#pragma unroll
            for (int j = 0; j < 7; j++)
#pragma unroll
                for (int v = 0; v < 4; v++) acc[i][j][v] = 0.f;
    };

    // ---- one-time loads: A (128 x 26 granules) + Gt resident (224 x 26) ----
    for (int i = 0; i < 7; i++) {
        int idx = tid + i * 512;
        if (idx < 128 * 26) {
            int r = idx / 26, gg = idx - r * 26;
            int c = gg >> 3, g = gg & 7;
            cp_async16(sb + SMEM_A_OFF + (uint32_t)c * A_CHUNK + swz(r, g),
                       A + (size_t)(m0 + r) * KPAD_CAP + gg * 8);
        }
    }
    for (int i = 0; i < 12; i++) {
        int idx = tid + i * 512;
        if (idx < 224 * 26) {
            int r = idx / 26, gg = idx - r * 26;
            uint32_t dst;
            if (gg < 24) dst = sb + GT_OFF + (uint32_t)(gg >> 3) * W_CHUNK + swz(r, gg & 7);
            else         dst = sb + GT_TAIL + (uint32_t)r * 32u + (uint32_t)(gg - 24) * 16u;
            cp_async16(dst, Gt + (size_t)r * KPAD_CAP + gg * 8);
        }
    }
    asm volatile("cp.async.commit_group;");
    asm volatile("cp.async.wait_group 0;");
    __syncthreads();

    for (int it = 0; it < NITER; it++) {
        const int last = (it == NITER - 1);

        // ============ phase 1: z = A @ Gt^T (resident, NO barriers) =======
        zero_acc();
        if (full_n) {
            for (int ch = 0; ch < 3; ch++) {
                const uint32_t sA = sb + SMEM_A_OFF + (uint32_t)ch * A_CHUNK;
                const uint32_t sW = sb + GT_OFF + (uint32_t)ch * W_CHUNK;
#pragma unroll
                for (int ks = 0; ks < 4; ks++) compute_ks7(sA, sW, ks);
            }
            tail7();
        } else {
            for (int ch = 0; ch < 3; ch++) {
                const uint32_t sA = sb + SMEM_A_OFF + (uint32_t)ch * A_CHUNK;
                const uint32_t sW = sb + GT_OFF + (uint32_t)ch * W_CHUNK;
#pragma unroll
                for (int ks = 0; ks < 4; ks++) compute_ks4(sA, sW, ks);
            }
            tail4();
        }

        // z -> smem (fp16), this warp's real cols only.
#pragma unroll
        for (int mf = 0; mf < 2; mf++)
#pragma unroll
        for (int nf = 0; nf < 7; nf++) {
            if (nf >= nfc) continue;
#pragma unroll
            for (int hf = 0; hf < 2; hf++) {
                int row = wm * 32 + mf * 16 + hf * 8 + (lane >> 2);
                int col = wn * 56 + nf * 8 + ((lane & 3) << 1);
                __half2 hv = __floats2half2_rn(acc[mf][nf][hf * 2], acc[mf][nf][hf * 2 + 1]);
                *(__half2*)(smem + SMEM_Z_OFF + (uint32_t)row * 448u + (uint32_t)col * 2u) = hv;
            }
        }
        __syncthreads();

        // ============ phase 2: scores + softmax (cols 0..199) ============
#pragma unroll
        for (int bi = 0; bi < 2; bi++) {
            int bb = wid * 2 + bi;
            float s[4][4], beta[4];
#pragma unroll
            for (int t = 0; t < 4; t++) {
                beta[t] = 0.f;
#pragma unroll
                for (int r = 0; r < 4; r++) s[t][r] = 0.f;
            }
            if (lane < 25) {
                float zf[4][8], vf[4][8], gf[8];
                int c = lane >> 3, g = lane & 7;
#pragma unroll
                for (int t = 0; t < 4; t++) {
                    int row = bb * 4 + t;
                    ld8h(zf[t], (const __half*)(smem + SMEM_Z_OFF + (uint32_t)row * 448u + (uint32_t)lane * 16u));
                    ld8h(vf[t], (const __half*)(smem + SMEM_A_OFF + (uint32_t)c * A_CHUNK + swz(row, g)));
                }
                float4 ga = *(const float4*)(g2 + lane * 8);
                float4 gb = *(const float4*)(g2 + lane * 8 + 4);
                gf[0]=ga.x; gf[1]=ga.y; gf[2]=ga.z; gf[3]=ga.w;
                gf[4]=gb.x; gf[5]=gb.y; gf[6]=gb.z; gf[7]=gb.w;
#pragma unroll
                for (int t = 0; t < 4; t++) {
#pragma unroll
                    for (int e = 0; e < 8; e++)
                        beta[t] = fmaf(vf[t][e], gf[e], beta[t]);
#pragma unroll
                    for (int r = 0; r < 4; r++) {
                        float a2 = 0.f;
#pragma unroll
                        for (int e = 0; e < 8; e++)
                            a2 = fmaf(zf[t][e], vf[r][e], a2);
                        s[t][r] = a2;
                    }
                }
            }
#pragma unroll
            for (int t = 0; t < 4; t++) {
#pragma unroll
                for (int off = 16; off > 0; off >>= 1)
                    beta[t] += __shfl_xor_sync(0xffffffffu, beta[t], off);
#pragma unroll
                for (int r = 0; r < 4; r++)
#pragma unroll
                    for (int off = 16; off > 0; off >>= 1)
                        s[t][r] += __shfl_xor_sync(0xffffffffu, s[t][r], off);
            }
            if (lane < 16) {
                int t = lane >> 2;
                float sc[4];
#pragma unroll
                for (int r = 0; r < 4; r++) sc[r] = s[t][r] + beta[r];
                float m = fmaxf(fmaxf(sc[0], sc[1]), fmaxf(sc[2], sc[3]));
                float e0 = expf(sc[0] - m), e1 = expf(sc[1] - m);
                float e2 = expf(sc[2] - m), e3 = expf(sc[3] - m);
                float inv = 1.f / (e0 + e1 + e2 + e3);
                float pe = (lane & 3) == 0 ? e0 : (lane & 3) == 1 ? e1 : (lane & 3) == 2 ? e2 : e3;
                *(float*)(smem + SMEM_P_OFF + (uint32_t)bb * 64u + (uint32_t)lane * 4u) = pe * inv;
            }
        }
        __syncthreads();   // all warps done with z (and probs visible)

        // ============ phase 3: u = A @ W3^T (W3 streamed via z region) ====
        zero_acc();
        load_w3(0);
        for (int ch = 0; ch < 4; ch++) {
            if (ch < 3) { load_w3(ch + 1); asm volatile("cp.async.wait_group 1;"); }
            else        { asm volatile("cp.async.wait_group 0;"); }
            __syncthreads();
            const uint32_t sA = sb + SMEM_A_OFF + (uint32_t)ch * A_CHUNK;
            const uint32_t sW = sb + SMEM_Z_OFF + (uint32_t)(ch & 1) * W_STAGE;
            const int nks = (ch < 3) ? 4 : 1;
            if (full_n) {
                for (int ks = 0; ks < nks; ks++) compute_ks7(sA, sW, ks);
            } else {
                for (int ks = 0; ks < nks; ks++) compute_ks4(sA, sW, ks);
            }
            __syncthreads();   // stage reuse + A-read completion before h write
        }

        // epilogue: h[t] = sum_s p[t][s] * (u[s] + b3) -> A smem (or D last)
#pragma unroll
        for (int mf = 0; mf < 2; mf++)
#pragma unroll
        for (int hf = 0; hf < 2; hf++) {
            int br = wm * 32 + mf * 16 + hf * 8 + (lane >> 2);
            int bb = br >> 2, t = br & 3;
            float4 pv = *(const float4*)(smem + SMEM_P_OFF + (uint32_t)bb * 64u + (uint32_t)t * 16u);
            int base = (lane >> 2) & 4;
#pragma unroll
            for (int nf = 0; nf < 7; nf++) {
                if (nf >= nfc) continue;
                int c0 = wn * 56 + nf * 8 + ((lane & 3) << 1);
                float hpair[2];
#pragma unroll
                for (int e = 0; e < 2; e++) {
                    float uv = acc[mf][nf][hf * 2 + e] + ((c0 + e < FV) ? b3[c0 + e] : 0.f);
                    float h = 0.f;
#pragma unroll
                    for (int s2 = 0; s2 < 4; s2++) {
                        float us = __shfl_sync(0xffffffffu, uv, ((base + s2) << 2) | (lane & 3));
                        float ps = (s2 == 0) ? pv.x : (s2 == 1) ? pv.y : (s2 == 2) ? pv.z : pv.w;
                        h = fmaf(ps, us, h);
                    }
                    hpair[e] = h;
                }
                if (c0 < FV) {
                    __half2 hv = __floats2half2_rn(hpair[0], hpair[1]);
                    if (last) {
                        *(__half2*)(D + (size_t)((m0 + br) >> 2) * FEAT + t * FV + c0) = hv;
                    } else {
                        int chk = c0 >> 6, cc = c0 & 63;
                        *(__half2*)(smem + SMEM_A_OFF + (uint32_t)chk * A_CHUNK
                                    + swz(br, cc >> 3) + (uint32_t)(cc & 7) * 2u) = hv;
                    }
                }
            }
        }
        if (!last) __syncthreads();
    }
}

// ----------------------- decoder GEMM (fp16 mma.sync, 2-stage) -------------
#define OFF_W 16384u
#define STAGE_BYTES 30720u
#define SMEM_BYTES 61440

__global__ __launch_bounds__(256, 2)
void gemm_mma(const __half* __restrict__ A, int lda,
              const __half* __restrict__ W, int ldw,
              const float* __restrict__ bias,
              __half* __restrict__ Ch, int ldc, int K, int n_real, int relu)
{
    extern __shared__ char smem[];
    const uint32_t sb = smem_u32(smem);
    const int tid = threadIdx.x;
    const int lane = tid & 31;
    const int wid = tid >> 5;
    const int wm = wid & 3;
    const int wn = wid >> 2;
    const int m0 = blockIdx.y * 128;
    const int n0 = blockIdx.x * 112;
    const int nfull = K >> 6;
    const int nch = nfull + 1;

    float acc[2][7][4];
#pragma unroll
    for (int i = 0; i < 2; i++)
#pragma unroll
        for (int j = 0; j < 7; j++)
#pragma unroll
            for (int v = 0; v < 4; v++) acc[i][j][v] = 0.f;

    auto load_full = [&](int ch) {
        const uint32_t s = sb + (uint32_t)(ch & 1) * STAGE_BYTES;
        const int kc = ch << 6;
#pragma unroll
        for (int i = 0; i < 4; i++) {
            int idx = tid + i * 256;
            int r = idx >> 3, g = idx & 7;
            cp_async16(s + swz(r, g), A + (size_t)(m0 + r) * lda + kc + g * 8);
        }
#pragma unroll
        for (int i = 0; i < 3; i++) {
            int idx = tid + i * 256;
            int r = idx >> 3, g = idx & 7;
            cp_async16(s + OFF_W + swz(r, g), W + (size_t)(n0 + r) * ldw + kc + g * 8);
        }
        {
            int idx = tid + 768;
            if (idx < 896) {
                int r = idx >> 3, g = idx & 7;
                cp_async16(s + OFF_W + swz(r, g), W + (size_t)(n0 + r) * ldw + kc + g * 8);
            }
        }
        asm volatile("cp.async.commit_group;");
    };
    auto load_tail = [&](int ch) {
        const uint32_t s = sb + (uint32_t)(ch & 1) * STAGE_BYTES;
        const int kc = ch << 6;
        {
            int r = tid >> 1, g = tid & 1;
            cp_async16(s + swz(r, g), A + (size_t)(m0 + r) * lda + kc + g * 8);
        }
        if (tid < 224) {
            int r = tid >> 1, g = tid & 1;
            cp_async16(s + OFF_W + swz(r, g), W + (size_t)(n0 + r) * ldw + kc + g * 8);
        }
        asm volatile("cp.async.commit_group;");
    };
    auto compute_ks = [&](uint32_t s, int ks) {
        uint32_t ah[2][4], bh[7][2];
        const uint32_t sw = s + OFF_W;
#pragma unroll
        for (int mf = 0; mf < 2; mf++) {
            int r = wm * 32 + mf * 16 + (lane & 15);
            int g = ks * 2 + (lane >> 4);
            ldsm_x4(ah[mf], s + swz(r, g));
        }
#pragma unroll
        for (int p = 0; p < 3; p++) {
            int r = wn * 56 + p * 16 + (lane & 7) + ((lane >> 4) & 1) * 8;
            int g = ks * 2 + ((lane >> 3) & 1);
            uint32_t t4[4];
            ldsm_x4(t4, sw + swz(r, g));
            bh[2*p][0] = t4[0]; bh[2*p][1] = t4[1];
            bh[2*p+1][0] = t4[2]; bh[2*p+1][1] = t4[3];
        }
        {
            int l15 = lane & 15;
            int r = wn * 56 + 48 + (l15 & 7);
            int g = ks * 2 + ((l15 >> 3) & 1);
            ldsm_x2(bh[6], sw + swz(r, g));
        }
#pragma unroll
        for (int mf = 0; mf < 2; mf++)
#pragma unroll
            for (int nf = 0; nf < 7; nf++)
                mma16816(acc[mf][nf], ah[mf], bh[nf]);
    };

    if (nfull > 0) load_full(0); else load_tail(0);
    for (int ch = 0; ch < nch; ch++) {
        if (ch + 1 < nch) {
            if (ch + 1 < nfull) load_full(ch + 1); else load_tail(ch + 1);
            asm volatile("cp.async.wait_group 1;");
        } else {
            asm volatile("cp.async.wait_group 0;");
        }
        __syncthreads();
        const uint32_t s = sb + (uint32_t)(ch & 1) * STAGE_BYTES;
        if (ch < nfull) {
#pragma unroll
            for (int ks = 0; ks < 4; ks++) compute_ks(s, ks);
        } else {
            compute_ks(s, 0);
        }
        if (ch + 1 < nch) __syncthreads();
    }

#pragma unroll
    for (int mf = 0; mf < 2; mf++)
#pragma unroll
    for (int nf = 0; nf < 7; nf++) {
        int r = m0 + wm * 32 + mf * 16 + (lane >> 2);
        int c = n0 + wn * 56 + nf * 8 + ((lane & 3) << 1);
#pragma unroll
        for (int hf = 0; hf < 2; hf++) {
            int rr = r + hf * 8;
#pragma unroll
            for (int e = 0; e < 2; e++) {
                int cc = c + e;
                if (cc >= n_real) continue;
                float v = acc[mf][nf][hf * 2 + e] + bias[cc];
                if (relu) v = fmaxf(v, 0.f);
                Ch[(size_t)rr * ldc + cc] = __float2half_rn(v);
            }
        }
    }
}

// ----------------------------- precompute ----------------------------------
__global__ void compute_gt(const float* __restrict__ W1, const float* __restrict__ W2,
                           const float* __restrict__ b1,
                           __half* __restrict__ gthi, float* __restrict__ g2)
{
    int idx = blockIdx.x * blockDim.x + threadIdx.x;
    if (idx < KPAD_CAP) {
        float s = 0.f;
        if (idx < FV)
            for (int j = 0; j < FV; j++) s = fmaf(b1[j], W2[(size_t)j * FV + idx], s);
        g2[idx] = s;
    }
    if (idx >= NPAD_CAP * KPAD_CAP) return;
    int n = idx / KPAD_CAP, k = idx % KPAD_CAP;
    float s = 0.f;
    if (n < FV && k < FV) {
        for (int j = 0; j < FV; j++)
            s = fmaf(W1[(size_t)j * FV + k], W2[(size_t)j * FV + n], s);
    }
    gthi[idx] = __float2half_rn(s);
}

__global__ void fold_head(const float* __restrict__ Wo, const float* __restrict__ Wd2,
                          const float* __restrict__ bd2, const float* __restrict__ bo,
                          float* __restrict__ Wop, float* __restrict__ bop)
{
    int idx = blockIdx.x * blockDim.x + threadIdx.x;
    if (idx < 10) {
        float s = bo[idx];
        for (int i = 0; i < FEAT; i++) s = fmaf(Wo[(size_t)idx * FEAT + i], bd2[i], s);
        bop[idx] = s;
    }
    if (idx >= 10 * FEAT) return;
    int j = idx / FEAT, k = idx % FEAT;
    float s = 0.f;
    for (int i = 0; i < FEAT; i++)
        s = fmaf(Wo[(size_t)j * FEAT + i], Wd2[(size_t)i * FEAT + k], s);
    Wop[idx] = s;
}

// ----------------------------- conversions --------------------------------
__global__ void convert_x_kernel(const float* __restrict__ x,
                                 __half* __restrict__ hhi)
{
    size_t idx = (size_t)blockIdx.x * blockDim.x + threadIdx.x;
    if (idx >= (size_t)BROWS * KPAD_CAP) return;
    size_t R = idx / KPAD_CAP;
    int f = (int)(idx % KPAD_CAP);
    hhi[idx] = __float2half_rn((f < FV) ? x[R * FV + f] : 0.f);
}

__global__ void convert_w_kernel(const float* __restrict__ W, int rin, int cin,
                                 __half* __restrict__ hi, int rout, int cout)
{
    int idx = blockIdx.x * blockDim.x + threadIdx.x;
    if (idx >= rout * cout) return;
    int r = idx / cout, c = idx % cout;
    float v = (r < rin && c < cin) ? W[(size_t)r * cin + c] : 0.f;
    hi[idx] = __float2half_rn(v);
}

// ----------------------------- head (fp16 activations, folded Wd2) ---------
__global__ __launch_bounds__(256)
void head_kernel(const __half* __restrict__ T, const float* __restrict__ Wop,
                 const float* __restrict__ bop, float* __restrict__ out)
{
    const int b    = blockIdx.x * 8 + threadIdx.y;
    const int lane = threadIdx.x;
    const __half* a = T + (size_t)b * FEAT;

    float acc[10];
#pragma unroll
    for (int j = 0; j < 10; j++) acc[j] = 0.f;
    for (int kk = lane; kk < FEAT; kk += 32) {
        float av = __half2float(a[kk]);
#pragma unroll
        for (int j = 0; j < 10; j++)
            acc[j] = fmaf(av, Wop[j * FEAT + kk], acc[j]);
    }
#pragma unroll
    for (int j = 0; j < 10; j++)
#pragma unroll
        for (int off = 16; off > 0; off >>= 1)
            acc[j] += __shfl_xor_sync(0xffffffffu, acc[j], off);

    if (lane == 0) {
        float v[10], m = -1e30f;
#pragma unroll
        for (int j = 0; j < 10; j++) { v[j] = acc[j] + bop[j]; m = fmaxf(m, v[j]); }
        float ssum = 0.f;
#pragma unroll
        for (int j = 0; j < 10; j++) { v[j] = expf(v[j] - m); ssum += v[j]; }
        float inv = 1.f / ssum;
#pragma unroll
        for (int j = 0; j < 10; j++) out[(size_t)b * 10 + j] = v[j] * inv;
    }
}

// ---------------------------------------------------------------------------
extern "C" void kernel_launch(void* const* d_in, const int* in_sizes, int n_in,
                              void* d_out, int out_size)
{
    const float* x   = (const float*)d_in[0];
    const float* W1  = (const float*)d_in[1];
    const float* b1  = (const float*)d_in[2];
    const float* W2  = (const float*)d_in[3];
    const float* W3  = (const float*)d_in[5];
    const float* b3  = (const float*)d_in[6];
    const float* Wd1 = (const float*)d_in[7];
    const float* bd1 = (const float*)d_in[8];
    const float* Wd2 = (const float*)d_in[9];
    const float* bd2 = (const float*)d_in[10];
    const float* Wo  = (const float*)d_in[11];
    const float* bo  = (const float*)d_in[12];
    float* out = (float*)d_out;

    cudaFuncSetAttribute(capsule_persist, cudaFuncAttributeMaxDynamicSharedMemorySize, CAP_SMEM);
    cudaFuncSetAttribute(gemm_mma, cudaFuncAttributeMaxDynamicSharedMemorySize, SMEM_BYTES);

    __half *hhi, *gthi, *w3hi, *wd1hi, *dhi, *thi;
    float *g2, *wop, *bop;
    cudaGetSymbolAddress((void**)&hhi, g_hhi);
    cudaGetSymbolAddress((void**)&g2, g_g2);
    cudaGetSymbolAddress((void**)&gthi, g_gthi);
    cudaGetSymbolAddress((void**)&w3hi, g_w3hi);
    cudaGetSymbolAddress((void**)&wd1hi, g_wd1hi);
    cudaGetSymbolAddress((void**)&wop, g_wop);
    cudaGetSymbolAddress((void**)&bop, g_bop);
    cudaGetSymbolAddress((void**)&dhi, g_dhi);
    cudaGetSymbolAddress((void**)&thi, g_thi);

    // precompute + conversions
    convert_x_kernel<<<(int)(((size_t)BROWS * KPAD_CAP + 255) / 256), 256>>>(x, hhi);
    int wcap = NPAD_CAP * KPAD_CAP;
    compute_gt<<<(wcap + 255) / 256, 256>>>(W1, W2, b1, gthi, g2);
    convert_w_kernel<<<(wcap + 255) / 256, 256>>>(W3, FV, FV, w3hi, NPAD_CAP, KPAD_CAP);

    // all 8 capsule iterations in ONE launch; A + Gt resident in smem
    capsule_persist<<<BROWS / 128, 512, CAP_SMEM>>>(hhi, gthi, w3hi, g2, b3, dhi);

    // decoder precompute
    int wdec = FEAT * FEAT;
    convert_w_kernel<<<(wdec + 255) / 256, 256>>>(Wd1, FEAT, FEAT, wd1hi, FEAT, FEAT);
    fold_head<<<(10 * FEAT + 255) / 256, 256>>>(Wo, Wd2, bd2, bo, wop, bop);

    // decoder layer 1 (fp16) + folded head
    const dim3 gdec(7, BATCH / 128);
    gemm_mma<<<gdec, 256, SMEM_BYTES>>>(dhi, FEAT, wd1hi, FEAT, bd1,
                                        thi, FEAT, FEAT, FEAT, 1);
    head_kernel<<<BATCH / 8, dim3(32, 8)>>>(thi, wop, bop, out);
}

// round 17
// speedup vs baseline: 1.1096x; 1.0291x over previous
#include <cuda_runtime.h>
#include <cuda_fp16.h>
#include <math.h>
#include <stdint.h>

#define BATCH 32768
#define FEAT  784
#define FV    196
#define NITER 8
#define BROWS (BATCH * 4)        // 131072 capsule rows

#define KPAD_CAP 208             // capsule K padded (3*64 + 16)
#define NPAD_CAP 224             // capsule weight buffer rows (pads zero)

// ----------------------------- scratch ------------------------------------
__device__ __align__(256) __half g_hhi [(size_t)BROWS * KPAD_CAP];
__device__ __align__(256) __half g_gthi[NPAD_CAP * KPAD_CAP];
__device__ __align__(256) __half g_w3hi[NPAD_CAP * KPAD_CAP];
__device__ __align__(256) __half g_wd1hi[FEAT * FEAT];
__device__ __align__(256) float  g_wop[10 * FEAT];
__device__ __align__(256) float  g_bop[16];
__device__ __align__(256) __half g_dhi[(size_t)BATCH * FEAT];
__device__ __align__(256) __half g_thi[(size_t)BATCH * FEAT];

// ----------------------------- PTX helpers --------------------------------
__device__ __forceinline__ uint32_t smem_u32(const void* p) {
    uint32_t a;
    asm("{ .reg .u64 t; cvta.to.shared.u64 t, %1; cvt.u32.u64 %0, t; }" : "=r"(a) : "l"(p));
    return a;
}
__device__ __forceinline__ void cp_async16(uint32_t dst, const void* src) {
    asm volatile("cp.async.cg.shared.global [%0], [%1], 16;" :: "r"(dst), "l"(src));
}
__device__ __forceinline__ void ldsm_x4(uint32_t* r, uint32_t addr) {
    asm volatile("ldmatrix.sync.aligned.m8n8.x4.shared.b16 {%0,%1,%2,%3}, [%4];"
                 : "=r"(r[0]), "=r"(r[1]), "=r"(r[2]), "=r"(r[3]) : "r"(addr));
}
__device__ __forceinline__ void ldsm_x2(uint32_t* r, uint32_t addr) {
    asm volatile("ldmatrix.sync.aligned.m8n8.x2.shared.b16 {%0,%1}, [%2];"
                 : "=r"(r[0]), "=r"(r[1]) : "r"(addr));
}
__device__ __forceinline__ void mma16816(float* c, const uint32_t* a, const uint32_t* b) {
    asm volatile("mma.sync.aligned.m16n8k16.row.col.f32.f16.f16.f32 "
                 "{%0,%1,%2,%3}, {%4,%5,%6,%7}, {%8,%9}, {%0,%1,%2,%3};"
                 : "+f"(c[0]), "+f"(c[1]), "+f"(c[2]), "+f"(c[3])
                 : "r"(a[0]), "r"(a[1]), "r"(a[2]), "r"(a[3]), "r"(b[0]), "r"(b[1]));
}
// swizzle for 128B rows, 16B granules
__device__ __forceinline__ uint32_t swz(int r, int g) {
    return (uint32_t)r * 128u + ((uint32_t)(g ^ (r & 7)) << 4);
}
// load 8 halves -> 8 floats (generic pointer)
__device__ __forceinline__ void ld8h(float* f, const __half* p) {
    uint4 q = *(const uint4*)p;
    const __half2* h = reinterpret_cast<const __half2*>(&q);
#pragma unroll
    for (int i = 0; i < 4; i++) {
        float2 a = __half22float2(h[i]);
        f[2*i] = a.x; f[2*i+1] = a.y;
    }
}

// ================== persistent fused capsule (all 8 iterations) ============
// One 512-thread block owns 128 rows (32 batches).
// Resident in smem: A (h state; col 196 holds constant 1.0), full Gt
// (row n col 196 holds g2[n] -> z' = z + beta free via MMA).
// N computed = 200: warps wn=0..2 do 7 n8-frags, wn=3 does 4 (static paths).
#define SMEM_A_OFF 0u
#define A_CHUNK    16384u               // one 64-col chunk of A (swz layout)
#define GT_OFF     65536u
#define W_CHUNK    28672u               // 224 rows x 128B
#define GT_TAIL    (GT_OFF + 3u * W_CHUNK)          // 151552, 224 x 32B
#define SMEM_Z_OFF 158720u              // 128 x 224 fp16, row stride 448B
#define W_STAGE    28672u               // W3 stages alias the z region
#define SMEM_P_OFF 216064u              // 32 batches x 16 floats
#define CAP_SMEM   218112

__global__ __launch_bounds__(512, 1)
void capsule_persist(const __half* __restrict__ A,
                     const __half* __restrict__ Gt,
                     const __half* __restrict__ W3,
                     const float* __restrict__ b3,
                     __half* __restrict__ D)
{
    extern __shared__ char smem[];
    const uint32_t sb = smem_u32(smem);
    const int tid = threadIdx.x;
    const int lane = tid & 31;
    const int wid = tid >> 5;        // 0..15
    const int wm = wid & 3;          // rows wm*32
    const int wn = wid >> 2;         // cols wn*56 (0..3)
    const int m0 = blockIdx.x * 128;
    const bool full_n = (wn < 3);    // warp-uniform
    const int nfc = full_n ? 7 : 4;  // cold-path guard only

    float acc[2][7][4];

    // stream W3 chunk ch into z-region stage (ch&1)
    auto load_w3 = [&](int ch) {
        const uint32_t s = sb + SMEM_Z_OFF + (uint32_t)(ch & 1) * W_STAGE;
        if (ch < 3) {
#pragma unroll
            for (int i = 0; i < 4; i++) {
                int idx = tid + i * 512;
                if (idx < 1792) {
                    int r = idx >> 3, g = idx & 7;
                    cp_async16(s + swz(r, g), W3 + (size_t)r * KPAD_CAP + (ch << 6) + g * 8);
                }
            }
        } else {
            if (tid < 448) {
                int r = tid >> 1, g = tid & 1;
                cp_async16(s + swz(r, g), W3 + (size_t)r * KPAD_CAP + 192 + g * 8);
            }
        }
        asm volatile("cp.async.commit_group;");
    };

    // ---- static k-step bodies (7-frag and 4-frag variants) ----
    auto compute_ks7 = [&](uint32_t sA, uint32_t sW, int ks) {
        uint32_t ah[2][4], bh[7][2];
#pragma unroll
        for (int mf = 0; mf < 2; mf++) {
            int r = wm * 32 + mf * 16 + (lane & 15);
            int g = ks * 2 + (lane >> 4);
            ldsm_x4(ah[mf], sA + swz(r, g));
        }
#pragma unroll
        for (int p = 0; p < 3; p++) {
            int r = wn * 56 + p * 16 + (lane & 7) + ((lane >> 4) & 1) * 8;
            int g = ks * 2 + ((lane >> 3) & 1);
            uint32_t t4[4];
            ldsm_x4(t4, sW + swz(r, g));
            bh[2*p][0] = t4[0]; bh[2*p][1] = t4[1];
            bh[2*p+1][0] = t4[2]; bh[2*p+1][1] = t4[3];
        }
        {
            int l15 = lane & 15;
            int r = wn * 56 + 48 + (l15 & 7);
            int g = ks * 2 + ((l15 >> 3) & 1);
            ldsm_x2(bh[6], sW + swz(r, g));
        }
#pragma unroll
        for (int mf = 0; mf < 2; mf++)
#pragma unroll
            for (int nf = 0; nf < 7; nf++)
                mma16816(acc[mf][nf], ah[mf], bh[nf]);
    };
    auto compute_ks4 = [&](uint32_t sA, uint32_t sW, int ks) {
        uint32_t ah[2][4], bh[4][2];
#pragma unroll
        for (int mf = 0; mf < 2; mf++) {
            int r = wm * 32 + mf * 16 + (lane & 15);
            int g = ks * 2 + (lane >> 4);
            ldsm_x4(ah[mf], sA + swz(r, g));
        }
#pragma unroll
        for (int p = 0; p < 2; p++) {
            int r = 168 + p * 16 + (lane & 7) + ((lane >> 4) & 1) * 8;
            int g = ks * 2 + ((lane >> 3) & 1);
            uint32_t t4[4];
            ldsm_x4(t4, sW + swz(r, g));
            bh[2*p][0] = t4[0]; bh[2*p][1] = t4[1];
            bh[2*p+1][0] = t4[2]; bh[2*p+1][1] = t4[3];
        }
#pragma unroll
        for (int mf = 0; mf < 2; mf++)
#pragma unroll
            for (int nf = 0; nf < 4; nf++)
                mma16816(acc[mf][nf], ah[mf], bh[nf]);
    };

    // Gt tail variants (compact 32B row stride)
    auto tail7 = [&]() {
        uint32_t ah[2][4], bh[7][2];
        const uint32_t sA = sb + SMEM_A_OFF + 3u * A_CHUNK;
        const uint32_t sT = sb + GT_TAIL;
#pragma unroll
        for (int mf = 0; mf < 2; mf++) {
            int r = wm * 32 + mf * 16 + (lane & 15);
            ldsm_x4(ah[mf], sA + swz(r, lane >> 4));
        }
#pragma unroll
        for (int p = 0; p < 3; p++) {
            int r = wn * 56 + p * 16 + (lane & 7) + ((lane >> 4) & 1) * 8;
            int g = ((lane >> 3) & 1);
            uint32_t t4[4];
            ldsm_x4(t4, sT + (uint32_t)r * 32u + (uint32_t)g * 16u);
            bh[2*p][0] = t4[0]; bh[2*p][1] = t4[1];
            bh[2*p+1][0] = t4[2]; bh[2*p+1][1] = t4[3];
        }
        {
            int l15 = lane & 15;
            int r = wn * 56 + 48 + (l15 & 7);
            int g = ((l15 >> 3) & 1);
            ldsm_x2(bh[6], sT + (uint32_t)r * 32u + (uint32_t)g * 16u);
        }
#pragma unroll
        for (int mf = 0; mf < 2; mf++)
#pragma unroll
            for (int nf = 0; nf < 7; nf++)
                mma16816(acc[mf][nf], ah[mf], bh[nf]);
    };
    auto tail4 = [&]() {
        uint32_t ah[2][4], bh[4][2];
        const uint32_t sA = sb + SMEM_A_OFF + 3u * A_CHUNK;
        const uint32_t sT = sb + GT_TAIL;
#pragma unroll
        for (int mf = 0; mf < 2; mf++) {
            int r = wm * 32 + mf * 16 + (lane & 15);
            ldsm_x4(ah[mf], sA + swz(r, lane >> 4));
        }
#pragma unroll
        for (int p = 0; p < 2; p++) {
            int r = 168 + p * 16 + (lane & 7) + ((lane >> 4) & 1) * 8;
            int g = ((lane >> 3) & 1);
            uint32_t t4[4];
            ldsm_x4(t4, sT + (uint32_t)r * 32u + (uint32_t)g * 16u);
            bh[2*p][0] = t4[0]; bh[2*p][1] = t4[1];
            bh[2*p+1][0] = t4[2]; bh[2*p+1][1] = t4[3];
        }
#pragma unroll
        for (int mf = 0; mf < 2; mf++)
#pragma unroll
            for (int nf = 0; nf < 4; nf++)
                mma16816(acc[mf][nf], ah[mf], bh[nf]);
    };

    auto zero_acc = [&]() {
#pragma unroll
        for (int i = 0; i < 2; i++)
#pragma unroll
            for (int j = 0; j < 7; j++)
#pragma unroll
                for (int v = 0; v < 4; v++) acc[i][j][v] = 0.f;
    };

    // ---- one-time loads: A (128 x 26 granules) + Gt resident (224 x 26) ----
    for (int i = 0; i < 7; i++) {
        int idx = tid + i * 512;
        if (idx < 128 * 26) {
            int r = idx / 26, gg = idx - r * 26;
            int c = gg >> 3, g = gg & 7;
            cp_async16(sb + SMEM_A_OFF + (uint32_t)c * A_CHUNK + swz(r, g),
                       A + (size_t)(m0 + r) * KPAD_CAP + gg * 8);
        }
    }
    for (int i = 0; i < 12; i++) {
        int idx = tid + i * 512;
        if (idx < 224 * 26) {
            int r = idx / 26, gg = idx - r * 26;
            uint32_t dst;
            if (gg < 24) dst = sb + GT_OFF + (uint32_t)(gg >> 3) * W_CHUNK + swz(r, gg & 7);
            else         dst = sb + GT_TAIL + (uint32_t)r * 32u + (uint32_t)(gg - 24) * 16u;
            cp_async16(dst, Gt + (size_t)r * KPAD_CAP + gg * 8);
        }
    }
    asm volatile("cp.async.commit_group;");
    asm volatile("cp.async.wait_group 0;");
    __syncthreads();

    for (int it = 0; it < NITER; it++) {
        const int last = (it == NITER - 1);

        // ============ phase 1: z' = A @ Gt^T (resident, NO barriers) ======
        zero_acc();
        if (full_n) {
            for (int ch = 0; ch < 3; ch++) {
                const uint32_t sA = sb + SMEM_A_OFF + (uint32_t)ch * A_CHUNK;
                const uint32_t sW = sb + GT_OFF + (uint32_t)ch * W_CHUNK;
#pragma unroll
                for (int ks = 0; ks < 4; ks++) compute_ks7(sA, sW, ks);
            }
            tail7();
        } else {
            for (int ch = 0; ch < 3; ch++) {
                const uint32_t sA = sb + SMEM_A_OFF + (uint32_t)ch * A_CHUNK;
                const uint32_t sW = sb + GT_OFF + (uint32_t)ch * W_CHUNK;
#pragma unroll
                for (int ks = 0; ks < 4; ks++) compute_ks4(sA, sW, ks);
            }
            tail4();
        }

        // z' -> smem (fp16), this warp's real cols only.
#pragma unroll
        for (int mf = 0; mf < 2; mf++)
#pragma unroll
        for (int nf = 0; nf < 7; nf++) {
            if (nf >= nfc) continue;
#pragma unroll
            for (int hf = 0; hf < 2; hf++) {
                int row = wm * 32 + mf * 16 + hf * 8 + (lane >> 2);
                int col = wn * 56 + nf * 8 + ((lane & 3) << 1);
                __half2 hv = __floats2half2_rn(acc[mf][nf][hf * 2], acc[mf][nf][hf * 2 + 1]);
                *(__half2*)(smem + SMEM_Z_OFF + (uint32_t)row * 448u + (uint32_t)col * 2u) = hv;
            }
        }
        __syncthreads();

        // ============ phase 2: scores + softmax (beta folded into z') =====
#pragma unroll
        for (int bi = 0; bi < 2; bi++) {
            int bb = wid * 2 + bi;
            float s[4][4];
#pragma unroll
            for (int t = 0; t < 4; t++)
#pragma unroll
                for (int r = 0; r < 4; r++) s[t][r] = 0.f;
            if (lane < 25) {
                float zf[4][8], vf[4][8];
                int c = lane >> 3, g = lane & 7;
#pragma unroll
                for (int t = 0; t < 4; t++) {
                    int row = bb * 4 + t;
                    ld8h(zf[t], (const __half*)(smem + SMEM_Z_OFF + (uint32_t)row * 448u + (uint32_t)lane * 16u));
                    ld8h(vf[t], (const __half*)(smem + SMEM_A_OFF + (uint32_t)c * A_CHUNK + swz(row, g)));
                }
#pragma unroll
                for (int t = 0; t < 4; t++)
#pragma unroll
                    for (int r = 0; r < 4; r++) {
                        float a2 = 0.f;
#pragma unroll
                        for (int e = 0; e < 8; e++)
                            a2 = fmaf(zf[t][e], vf[r][e], a2);
                        s[t][r] = a2;
                    }
            }
#pragma unroll
            for (int t = 0; t < 4; t++)
#pragma unroll
                for (int r = 0; r < 4; r++)
#pragma unroll
                    for (int off = 16; off > 0; off >>= 1)
                        s[t][r] += __shfl_xor_sync(0xffffffffu, s[t][r], off);
            if (lane < 16) {
                int t = lane >> 2;
                float sc[4];
#pragma unroll
                for (int r = 0; r < 4; r++) sc[r] = s[t][r];
                float m = fmaxf(fmaxf(sc[0], sc[1]), fmaxf(sc[2], sc[3]));
                float e0 = expf(sc[0] - m), e1 = expf(sc[1] - m);
                float e2 = expf(sc[2] - m), e3 = expf(sc[3] - m);
                float inv = 1.f / (e0 + e1 + e2 + e3);
                float pe = (lane & 3) == 0 ? e0 : (lane & 3) == 1 ? e1 : (lane & 3) == 2 ? e2 : e3;
                *(float*)(smem + SMEM_P_OFF + (uint32_t)bb * 64u + (uint32_t)lane * 4u) = pe * inv;
            }
        }
        __syncthreads();   // all warps done with z (and probs visible)

        // ============ phase 3: u = A @ W3^T (W3 streamed via z region) ====
        zero_acc();
        load_w3(0);
        for (int ch = 0; ch < 4; ch++) {
            if (ch < 3) { load_w3(ch + 1); asm volatile("cp.async.wait_group 1;"); }
            else        { asm volatile("cp.async.wait_group 0;"); }
            __syncthreads();
            const uint32_t sA = sb + SMEM_A_OFF + (uint32_t)ch * A_CHUNK;
            const uint32_t sW = sb + SMEM_Z_OFF + (uint32_t)(ch & 1) * W_STAGE;
            const int nks = (ch < 3) ? 4 : 1;
            if (full_n) {
                for (int ks = 0; ks < nks; ks++) compute_ks7(sA, sW, ks);
            } else {
                for (int ks = 0; ks < nks; ks++) compute_ks4(sA, sW, ks);
            }
            __syncthreads();
        }

        // epilogue: h[t] = sum_s p[t][s] * (u[s] + b3); half2-packed shuffles
#pragma unroll
        for (int mf = 0; mf < 2; mf++)
#pragma unroll
        for (int hf = 0; hf < 2; hf++) {
            int br = wm * 32 + mf * 16 + hf * 8 + (lane >> 2);
            int bb = br >> 2, t = br & 3;
            float4 pv = *(const float4*)(smem + SMEM_P_OFF + (uint32_t)bb * 64u + (uint32_t)t * 16u);
            int base = (lane >> 2) & 4;
#pragma unroll
            for (int nf = 0; nf < 7; nf++) {
                if (nf >= nfc) continue;
                int c0 = wn * 56 + nf * 8 + ((lane & 3) << 1);
                float u0 = acc[mf][nf][hf * 2]     + ((c0 < FV)     ? b3[c0]     : 0.f);
                float u1 = acc[mf][nf][hf * 2 + 1] + ((c0 + 1 < FV) ? b3[c0 + 1] : 0.f);
                __half2 up = __floats2half2_rn(u0, u1);
                uint32_t upk = *(uint32_t*)&up;
                float h0 = 0.f, h1 = 0.f;
#pragma unroll
                for (int s2 = 0; s2 < 4; s2++) {
                    uint32_t us = __shfl_sync(0xffffffffu, upk, ((base + s2) << 2) | (lane & 3));
                    __half2 uh = *(__half2*)&us;
                    float2 uf = __half22float2(uh);
                    float ps = (s2 == 0) ? pv.x : (s2 == 1) ? pv.y : (s2 == 2) ? pv.z : pv.w;
                    h0 = fmaf(ps, uf.x, h0);
                    h1 = fmaf(ps, uf.y, h1);
                }
                if (c0 < FV) {
                    __half2 hv = __floats2half2_rn(h0, h1);
                    if (last) {
                        *(__half2*)(D + (size_t)((m0 + br) >> 2) * FEAT + t * FV + c0) = hv;
                    } else {
                        int chk = c0 >> 6, cc = c0 & 63;
                        *(__half2*)(smem + SMEM_A_OFF + (uint32_t)chk * A_CHUNK
                                    + swz(br, cc >> 3) + (uint32_t)(cc & 7) * 2u) = hv;
                    }
                }
            }
        }
        if (!last) __syncthreads();
    }
}

// ----------------------- decoder GEMM (fp16 mma.sync, 2-stage) -------------
#define OFF_W 16384u
#define STAGE_BYTES 30720u
#define SMEM_BYTES 61440

__global__ __launch_bounds__(256, 2)
void gemm_mma(const __half* __restrict__ A, int lda,
              const __half* __restrict__ W, int ldw,
              const float* __restrict__ bias,
              __half* __restrict__ Ch, int ldc, int K, int n_real, int relu)
{
    extern __shared__ char smem[];
    const uint32_t sb = smem_u32(smem);
    const int tid = threadIdx.x;
    const int lane = tid & 31;
    const int wid = tid >> 5;
    const int wm = wid & 3;
    const int wn = wid >> 2;
    const int m0 = blockIdx.y * 128;
    const int n0 = blockIdx.x * 112;
    const int nfull = K >> 6;
    const int nch = nfull + 1;

    float acc[2][7][4];
#pragma unroll
    for (int i = 0; i < 2; i++)
#pragma unroll
        for (int j = 0; j < 7; j++)
#pragma unroll
            for (int v = 0; v < 4; v++) acc[i][j][v] = 0.f;

    auto load_full = [&](int ch) {
        const uint32_t s = sb + (uint32_t)(ch & 1) * STAGE_BYTES;
        const int kc = ch << 6;
#pragma unroll
        for (int i = 0; i < 4; i++) {
            int idx = tid + i * 256;
            int r = idx >> 3, g = idx & 7;
            cp_async16(s + swz(r, g), A + (size_t)(m0 + r) * lda + kc + g * 8);
        }
#pragma unroll
        for (int i = 0; i < 3; i++) {
            int idx = tid + i * 256;
            int r = idx >> 3, g = idx & 7;
            cp_async16(s + OFF_W + swz(r, g), W + (size_t)(n0 + r) * ldw + kc + g * 8);
        }
        {
            int idx = tid + 768;
            if (idx < 896) {
                int r = idx >> 3, g = idx & 7;
                cp_async16(s + OFF_W + swz(r, g), W + (size_t)(n0 + r) * ldw + kc + g * 8);
            }
        }
        asm volatile("cp.async.commit_group;");
    };
    auto load_tail = [&](int ch) {
        const uint32_t s = sb + (uint32_t)(ch & 1) * STAGE_BYTES;
        const int kc = ch << 6;
        {
            int r = tid >> 1, g = tid & 1;
            cp_async16(s + swz(r, g), A + (size_t)(m0 + r) * lda + kc + g * 8);
        }
        if (tid < 224) {
            int r = tid >> 1, g = tid & 1;
            cp_async16(s + OFF_W + swz(r, g), W + (size_t)(n0 + r) * ldw + kc + g * 8);
        }
        asm volatile("cp.async.commit_group;");
    };
    auto compute_ks = [&](uint32_t s, int ks) {
        uint32_t ah[2][4], bh[7][2];
        const uint32_t sw = s + OFF_W;
#pragma unroll
        for (int mf = 0; mf < 2; mf++) {
            int r = wm * 32 + mf * 16 + (lane & 15);
            int g = ks * 2 + (lane >> 4);
            ldsm_x4(ah[mf], s + swz(r, g));
        }
#pragma unroll
        for (int p = 0; p < 3; p++) {
            int r = wn * 56 + p * 16 + (lane & 7) + ((lane >> 4) & 1) * 8;
            int g = ks * 2 + ((lane >> 3) & 1);
            uint32_t t4[4];
            ldsm_x4(t4, sw + swz(r, g));
            bh[2*p][0] = t4[0]; bh[2*p][1] = t4[1];
            bh[2*p+1][0] = t4[2]; bh[2*p+1][1] = t4[3];
        }
        {
            int l15 = lane & 15;
            int r = wn * 56 + 48 + (l15 & 7);
            int g = ks * 2 + ((l15 >> 3) & 1);
            ldsm_x2(bh[6], sw + swz(r, g));
        }
#pragma unroll
        for (int mf = 0; mf < 2; mf++)
#pragma unroll
            for (int nf = 0; nf < 7; nf++)
                mma16816(acc[mf][nf], ah[mf], bh[nf]);
    };

    if (nfull > 0) load_full(0); else load_tail(0);
    for (int ch = 0; ch < nch; ch++) {
        if (ch + 1 < nch) {
            if (ch + 1 < nfull) load_full(ch + 1); else load_tail(ch + 1);
            asm volatile("cp.async.wait_group 1;");
        } else {
            asm volatile("cp.async.wait_group 0;");
        }
        __syncthreads();
        const uint32_t s = sb + (uint32_t)(ch & 1) * STAGE_BYTES;
        if (ch < nfull) {
#pragma unroll
            for (int ks = 0; ks < 4; ks++) compute_ks(s, ks);
        } else {
            compute_ks(s, 0);
        }
        if (ch + 1 < nch) __syncthreads();
    }

#pragma unroll
    for (int mf = 0; mf < 2; mf++)
#pragma unroll
    for (int nf = 0; nf < 7; nf++) {
        int r = m0 + wm * 32 + mf * 16 + (lane >> 2);
        int c = n0 + wn * 56 + nf * 8 + ((lane & 3) << 1);
#pragma unroll
        for (int hf = 0; hf < 2; hf++) {
            int rr = r + hf * 8;
#pragma unroll
            for (int e = 0; e < 2; e++) {
                int cc = c + e;
                if (cc >= n_real) continue;
                float v = acc[mf][nf][hf * 2 + e] + bias[cc];
                if (relu) v = fmaxf(v, 0.f);
                Ch[(size_t)rr * ldc + cc] = __float2half_rn(v);
            }
        }
    }
}

// ----------------------------- precompute ----------------------------------
// Gt[n,k] = sum_j W1[j,k]*W2[j,n] for k<196; Gt[n,196] = g2[n] = sum_j b1[j]*W2[j,n]
__global__ void compute_gt(const float* __restrict__ W1, const float* __restrict__ W2,
                           const float* __restrict__ b1, __half* __restrict__ gthi)
{
    int idx = blockIdx.x * blockDim.x + threadIdx.x;
    if (idx >= NPAD_CAP * KPAD_CAP) return;
    int n = idx / KPAD_CAP, k = idx % KPAD_CAP;
    float s = 0.f;
    if (n < FV && k < FV) {
        for (int j = 0; j < FV; j++)
            s = fmaf(W1[(size_t)j * FV + k], W2[(size_t)j * FV + n], s);
    } else if (n < FV && k == FV) {
        for (int j = 0; j < FV; j++)
            s = fmaf(b1[j], W2[(size_t)j * FV + n], s);
    }
    gthi[idx] = __float2half_rn(s);
}

__global__ void fold_head(const float* __restrict__ Wo, const float* __restrict__ Wd2,
                          const float* __restrict__ bd2, const float* __restrict__ bo,
                          float* __restrict__ Wop, float* __restrict__ bop)
{
    int idx = blockIdx.x * blockDim.x + threadIdx.x;
    if (idx < 10) {
        float s = bo[idx];
        for (int i = 0; i < FEAT; i++) s = fmaf(Wo[(size_t)idx * FEAT + i], bd2[i], s);
        bop[idx] = s;
    }
    if (idx >= 10 * FEAT) return;
    int j = idx / FEAT, k = idx % FEAT;
    float s = 0.f;
    for (int i = 0; i < FEAT; i++)
        s = fmaf(Wo[(size_t)j * FEAT + i], Wd2[(size_t)i * FEAT + k], s);
    Wop[idx] = s;
}

// ----------------------------- conversions --------------------------------
// col 196 carries constant 1.0 (beta fold); cols 197..207 zero.
__global__ void convert_x_kernel(const float* __restrict__ x,
                                 __half* __restrict__ hhi)
{
    size_t idx = (size_t)blockIdx.x * blockDim.x + threadIdx.x;
    if (idx >= (size_t)BROWS * KPAD_CAP) return;
    size_t R = idx / KPAD_CAP;
    int f = (int)(idx % KPAD_CAP);
    float v = (f < FV) ? x[R * FV + f] : ((f == FV) ? 1.f : 0.f);
    hhi[idx] = __float2half_rn(v);
}

__global__ void convert_w_kernel(const float* __restrict__ W, int rin, int cin,
                                 __half* __restrict__ hi, int rout, int cout)
{
    int idx = blockIdx.x * blockDim.x + threadIdx.x;
    if (idx >= rout * cout) return;
    int r = idx / cout, c = idx % cout;
    float v = (r < rin && c < cin) ? W[(size_t)r * cin + c] : 0.f;
    hi[idx] = __float2half_rn(v);
}

// ----------------------------- head (fp16 activations, folded Wd2) ---------
__global__ __launch_bounds__(256)
void head_kernel(const __half* __restrict__ T, const float* __restrict__ Wop,
                 const float* __restrict__ bop, float* __restrict__ out)
{
    const int b    = blockIdx.x * 8 + threadIdx.y;
    const int lane = threadIdx.x;
    const __half* a = T + (size_t)b * FEAT;

    float acc[10];
#pragma unroll
    for (int j = 0; j < 10; j++) acc[j] = 0.f;

    // 784 = 3*256 + 16; vectorized 8 halves/lane/iter
#pragma unroll
    for (int itc = 0; itc < 3; itc++) {
        int k0 = itc * 256 + lane * 8;
        float av[8];
        ld8h(av, a + k0);
#pragma unroll
        for (int j = 0; j < 10; j++) {
            const float* w = Wop + j * FEAT + k0;
            float4 w0 = *(const float4*)w;
            float4 w1 = *(const float4*)(w + 4);
            acc[j] = fmaf(av[0], w0.x, acc[j]); acc[j] = fmaf(av[1], w0.y, acc[j]);
            acc[j] = fmaf(av[2], w0.z, acc[j]); acc[j] = fmaf(av[3], w0.w, acc[j]);
            acc[j] = fmaf(av[4], w1.x, acc[j]); acc[j] = fmaf(av[5], w1.y, acc[j]);
            acc[j] = fmaf(av[6], w1.z, acc[j]); acc[j] = fmaf(av[7], w1.w, acc[j]);
        }
    }
    if (lane < 2) {
        int k0 = 768 + lane * 8;
        float av[8];
        ld8h(av, a + k0);
#pragma unroll
        for (int j = 0; j < 10; j++) {
            const float* w = Wop + j * FEAT + k0;
            float4 w0 = *(const float4*)w;
            float4 w1 = *(const float4*)(w + 4);
            acc[j] = fmaf(av[0], w0.x, acc[j]); acc[j] = fmaf(av[1], w0.y, acc[j]);
            acc[j] = fmaf(av[2], w0.z, acc[j]); acc[j] = fmaf(av[3], w0.w, acc[j]);
            acc[j] = fmaf(av[4], w1.x, acc[j]); acc[j] = fmaf(av[5], w1.y, acc[j]);
            acc[j] = fmaf(av[6], w1.z, acc[j]); acc[j] = fmaf(av[7], w1.w, acc[j]);
        }
    }
#pragma unroll
    for (int j = 0; j < 10; j++)
#pragma unroll
        for (int off = 16; off > 0; off >>= 1)
            acc[j] += __shfl_xor_sync(0xffffffffu, acc[j], off);

    if (lane == 0) {
        float v[10], m = -1e30f;
#pragma unroll
        for (int j = 0; j < 10; j++) { v[j] = acc[j] + bop[j]; m = fmaxf(m, v[j]); }
        float ssum = 0.f;
#pragma unroll
        for (int j = 0; j < 10; j++) { v[j] = expf(v[j] - m); ssum += v[j]; }
        float inv = 1.f / ssum;
#pragma unroll
        for (int j = 0; j < 10; j++) out[(size_t)b * 10 + j] = v[j] * inv;
    }
}

// ---------------------------------------------------------------------------
extern "C" void kernel_launch(void* const* d_in, const int* in_sizes, int n_in,
                              void* d_out, int out_size)
{
    const float* x   = (const float*)d_in[0];
    const float* W1  = (const float*)d_in[1];
    const float* b1  = (const float*)d_in[2];
    const float* W2  = (const float*)d_in[3];
    const float* W3  = (const float*)d_in[5];
    const float* b3  = (const float*)d_in[6];
    const float* Wd1 = (const float*)d_in[7];
    const float* bd1 = (const float*)d_in[8];
    const float* Wd2 = (const float*)d_in[9];
    const float* bd2 = (const float*)d_in[10];
    const float* Wo  = (const float*)d_in[11];
    const float* bo  = (const float*)d_in[12];
    float* out = (float*)d_out;

    cudaFuncSetAttribute(capsule_persist, cudaFuncAttributeMaxDynamicSharedMemorySize, CAP_SMEM);
    cudaFuncSetAttribute(gemm_mma, cudaFuncAttributeMaxDynamicSharedMemorySize, SMEM_BYTES);

    __half *hhi, *gthi, *w3hi, *wd1hi, *dhi, *thi;
    float *wop, *bop;
    cudaGetSymbolAddress((void**)&hhi, g_hhi);
    cudaGetSymbolAddress((void**)&gthi, g_gthi);
    cudaGetSymbolAddress((void**)&w3hi, g_w3hi);
    cudaGetSymbolAddress((void**)&wd1hi, g_wd1hi);
    cudaGetSymbolAddress((void**)&wop, g_wop);
    cudaGetSymbolAddress((void**)&bop, g_bop);
    cudaGetSymbolAddress((void**)&dhi, g_dhi);
    cudaGetSymbolAddress((void**)&thi, g_thi);

    // precompute + conversions
    convert_x_kernel<<<(int)(((size_t)BROWS * KPAD_CAP + 255) / 256), 256>>>(x, hhi);
    int wcap = NPAD_CAP * KPAD_CAP;
    compute_gt<<<(wcap + 255) / 256, 256>>>(W1, W2, b1, gthi);
    convert_w_kernel<<<(wcap + 255) / 256, 256>>>(W3, FV, FV, w3hi, NPAD_CAP, KPAD_CAP);

    // all 8 capsule iterations in ONE launch; A + Gt resident in smem
    capsule_persist<<<BROWS / 128, 512, CAP_SMEM>>>(hhi, gthi, w3hi, b3, dhi);

    // decoder precompute
    int wdec = FEAT * FEAT;
    convert_w_kernel<<<(wdec + 255) / 256, 256>>>(Wd1, FEAT, FEAT, wd1hi, FEAT, FEAT);
    fold_head<<<(10 * FEAT + 255) / 256, 256>>>(Wo, Wd2, bd2, bo, wop, bop);

    // decoder layer 1 (fp16) + folded head
    const dim3 gdec(7, BATCH / 128);
    gemm_mma<<<gdec, 256, SMEM_BYTES>>>(dhi, FEAT, wd1hi, FEAT, bd1,
                                        thi, FEAT, FEAT, FEAT, 1);
    head_kernel<<<BATCH / 8, dim3(32, 8)>>>(thi, wop, bop, out);
}